// round 6
// baseline (speedup 1.0000x reference)
#include <cuda_runtime.h>
#include <math.h>
#include <cstdint>

// Problem constants: B=4, L=2048, D=1024, H=16, Dh=64, 3D=3072
#define BATCH   4
#define SEQ     2048
#define EMBD    1024
#define NHEAD   16
#define HDIM    64
#define TOKENS  (BATCH * SEQ)            // 8192
#define QKVDIM  (3 * EMBD)               // 3072

// ---------------- scratch (static __device__, no allocation) ----------------
__device__ float g_q[(size_t)BATCH * NHEAD * SEQ * HDIM]; // [B,H,L,Dh] tf32, /8
__device__ float g_k[(size_t)BATCH * NHEAD * SEQ * HDIM]; // tf32
__device__ float g_v[(size_t)BATCH * NHEAD * SEQ * HDIM]; // tf32
__device__ float g_att[(size_t)TOKENS * EMBD];            // [B,L,D] tf32
__device__ float2 g_rope[(size_t)SEQ * 32];               // cos/sin table
__device__ float g_xc[(size_t)TOKENS * EMBD];             // x rounded to tf32
__device__ float g_wqkv[(size_t)EMBD * QKVDIM];           // W_qkv tf32
__device__ float g_wproj[(size_t)EMBD * EMBD];            // W_proj tf32

// ---------------- helpers ----------------------------------------------
__device__ __forceinline__ uint32_t f2tf32(float x) {
  uint32_t u;
  asm("cvt.rna.tf32.f32 %0, %1;" : "=r"(u) : "f"(x));
  return u;
}
__device__ __forceinline__ float f2tf32f(float x) {
  return __uint_as_float(f2tf32(x));
}

__device__ __forceinline__ void mma_tf32(float* d, const uint32_t* a,
                                         const uint32_t* b) {
  asm volatile(
      "mma.sync.aligned.m16n8k8.row.col.f32.tf32.tf32.f32 "
      "{%0,%1,%2,%3},{%4,%5,%6,%7},{%8,%9},{%0,%1,%2,%3};"
      : "+f"(d[0]), "+f"(d[1]), "+f"(d[2]), "+f"(d[3])
      : "r"(a[0]), "r"(a[1]), "r"(a[2]), "r"(a[3]), "r"(b[0]), "r"(b[1]));
}

#define CPA16(dst, src) \
  asm volatile("cp.async.cg.shared.global [%0], [%1], 16;\n" ::"r"(dst), "l"(src))

// ---------------- tf32 rounding kernel (grid-stride, float4) ----------------
__global__ __launch_bounds__(256) void tf32_round_kernel(
    const float* __restrict__ in, float* __restrict__ out, int n4) {
  int i = blockIdx.x * 256 + threadIdx.x;
  const int stride = gridDim.x * 256;
  for (; i < n4; i += stride) {
    float4 v = ((const float4*)in)[i];
    v.x = f2tf32f(v.x);
    v.y = f2tf32f(v.y);
    v.z = f2tf32f(v.z);
    v.w = f2tf32f(v.w);
    ((float4*)out)[i] = v;
  }
}

// ---------------- RoPE cos/sin table ----------------------------------------
__global__ __launch_bounds__(256) void rope_table_kernel() {
  const int idx = blockIdx.x * 256 + threadIdx.x;  // 0..65535
  const int l = idx >> 5, i = idx & 31;
  const float inv_freq = 1.0f / powf(10000.0f, (2.0f * (float)i) / 64.0f);
  float s, c;
  sincosf((float)l * inv_freq, &s, &c);
  g_rope[idx] = make_float2(c, s);
}

// ---------------- GEMM core (shared by both GEMM kernels) -------------------
#define A_STRIDE 36
#define B_STRIDE 136
#define A_BUF_FLOATS (128 * A_STRIDE)   // 4608
#define B_BUF_FLOATS (32 * B_STRIDE)    // 4352
#define GEMM_SMEM ((2 * (A_BUF_FLOATS + B_BUF_FLOATS)) * 4)  // 71680 B

__device__ __forceinline__ void gemm_tile_compute(
    const float* __restrict__ A, const float* __restrict__ B, float* sm,
    int m0, int n0, int N, int K, float acc[4][4][4]) {
  const int tid = threadIdx.x;
  const int warp = tid >> 5, lane = tid & 31;
  const int wm = warp >> 2, wn = warp & 3;
  const int g = lane >> 2, tig = lane & 3;

#pragma unroll
  for (int i = 0; i < 4; i++)
#pragma unroll
    for (int j = 0; j < 4; j++)
#pragma unroll
      for (int t = 0; t < 4; t++) acc[i][j][t] = 0.0f;

  auto prefetch = [&](int kt, int buf) {
    float* As = sm + buf * A_BUF_FLOATS;
    float* Bs = sm + 2 * A_BUF_FLOATS + buf * B_BUF_FLOATS;
    const int k0 = kt << 5;
#pragma unroll
    for (int j = 0; j < 4; j++) {
      const int p = tid + (j << 8);
      const int ar = p >> 3, ac = (p & 7) << 2;
      uint32_t da = (uint32_t)__cvta_generic_to_shared(As + ar * A_STRIDE + ac);
      CPA16(da, A + (size_t)(m0 + ar) * K + k0 + ac);
      const int br = p >> 5, bc = (p & 31) << 2;
      uint32_t db = (uint32_t)__cvta_generic_to_shared(Bs + br * B_STRIDE + bc);
      CPA16(db, B + (size_t)(k0 + br) * N + n0 + bc);
    }
    asm volatile("cp.async.commit_group;\n");
  };

  const int NT = K >> 5;
  prefetch(0, 0);

  for (int kt = 0; kt < NT; kt++) {
    const int buf = kt & 1;
    if (kt + 1 < NT) {
      prefetch(kt + 1, buf ^ 1);
      asm volatile("cp.async.wait_group 1;\n");
    } else {
      asm volatile("cp.async.wait_group 0;\n");
    }
    __syncthreads();

    const float* As = sm + buf * A_BUF_FLOATS;
    const float* Bs = sm + 2 * A_BUF_FLOATS + buf * B_BUF_FLOATS;

#pragma unroll
    for (int ks = 0; ks < 4; ks++) {
      const int kk = ks << 3;
      uint32_t af[4][4], bf[4][2];
#pragma unroll
      for (int mt = 0; mt < 4; mt++) {
        const float* ap = As + (wm * 64 + mt * 16 + g) * A_STRIDE + kk + tig;
        af[mt][0] = __float_as_uint(ap[0]);
        af[mt][2] = __float_as_uint(ap[4]);
        af[mt][1] = __float_as_uint(ap[8 * A_STRIDE]);
        af[mt][3] = __float_as_uint(ap[8 * A_STRIDE + 4]);
      }
#pragma unroll
      for (int nt = 0; nt < 4; nt++) {
        const float* bp = Bs + (kk + tig) * B_STRIDE + wn * 32 + nt * 8 + g;
        bf[nt][0] = __float_as_uint(bp[0]);
        bf[nt][1] = __float_as_uint(bp[4 * B_STRIDE]);
      }
#pragma unroll
      for (int mt = 0; mt < 4; mt++)
#pragma unroll
        for (int nt = 0; nt < 4; nt++) mma_tf32(acc[mt][nt], af[mt], bf[nt]);
    }
    __syncthreads();
  }
}

// ---------------- plain GEMM + bias (used for proj) -------------------------
__global__ __launch_bounds__(256) void gemm_tf32_kernel(
    const float* __restrict__ A, const float* __restrict__ B,
    const float* __restrict__ bias, float* __restrict__ C,
    int M, int N, int K) {
  extern __shared__ float sm[];
  const int tid = threadIdx.x;
  const int warp = tid >> 5, lane = tid & 31;
  const int wm = warp >> 2, wn = warp & 3;
  const int g = lane >> 2, tig = lane & 3;
  const int m0 = blockIdx.y << 7, n0 = blockIdx.x << 7;

  float acc[4][4][4];
  gemm_tile_compute(A, B, sm, m0, n0, N, K, acc);

#pragma unroll
  for (int mt = 0; mt < 4; mt++) {
    const int r = m0 + wm * 64 + mt * 16 + g;
#pragma unroll
    for (int nt = 0; nt < 4; nt++) {
      const int c = n0 + wn * 32 + nt * 8 + 2 * tig;
      const float b0 = __ldg(bias + c), b1 = __ldg(bias + c + 1);
      float2 v0 = {acc[mt][nt][0] + b0, acc[mt][nt][1] + b1};
      float2 v1 = {acc[mt][nt][2] + b0, acc[mt][nt][3] + b1};
      *(float2*)(C + (size_t)r * N + c) = v0;
      *(float2*)(C + (size_t)(r + 8) * N + c) = v1;
    }
  }
}

// ---------------- QKV GEMM with fused RoPE/split epilogue -------------------
__global__ __launch_bounds__(256) void gemm_qkv_rope_kernel(
    const float* __restrict__ A, const float* __restrict__ B,
    const float* __restrict__ bias, float* __restrict__ Q,
    float* __restrict__ K, float* __restrict__ V) {
  extern __shared__ float sm[];
  const int tid = threadIdx.x;
  const int warp = tid >> 5, lane = tid & 31;
  const int wm = warp >> 2, wn = warp & 3;
  const int g = lane >> 2, tig = lane & 3;
  const int m0 = blockIdx.y << 7, n0 = blockIdx.x << 7;

  float acc[4][4][4];
  gemm_tile_compute(A, B, sm, m0, n0, QKVDIM, EMBD, acc);

  const int seg = n0 >> 10;  // 0=q, 1=k, 2=v (block-uniform)
  float* dst = (seg == 0) ? Q : (seg == 1) ? K : V;

#pragma unroll
  for (int mt = 0; mt < 4; mt++) {
    const int r = m0 + wm * 64 + mt * 16 + g;  // token row (and r+8)
#pragma unroll
    for (int nt = 0; nt < 4; nt++) {
      const int c = n0 + wn * 32 + nt * 8 + 2 * tig;  // even column
      const float b0 = __ldg(bias + c), b1 = __ldg(bias + c + 1);
      const int d = c & 63;            // dim within head (even)
      const int h = (c & 1023) >> 6;   // head
      const int i = d >> 1;            // rope pair index
      float vals[2][2] = {{acc[mt][nt][0] + b0, acc[mt][nt][1] + b1},
                          {acc[mt][nt][2] + b0, acc[mt][nt][3] + b1}};
#pragma unroll
      for (int rr = 0; rr < 2; rr++) {
        const int m = r + rr * 8;
        const int bb = m >> 11, l = m & 2047;
        float* o = dst + ((size_t)(bb * NHEAD + h) * SEQ + l) * HDIM + d;
        const float x1 = vals[rr][0], x2 = vals[rr][1];
        float2 w;
        if (seg == 0) {
          const float2 cs = g_rope[l * 32 + i];
          w.x = f2tf32f((x1 * cs.x - x2 * cs.y) * 0.125f);
          w.y = f2tf32f((x1 * cs.y + x2 * cs.x) * 0.125f);
        } else if (seg == 1) {
          const float2 cs = g_rope[l * 32 + i];
          w.x = f2tf32f(x1 * cs.x - x2 * cs.y);
          w.y = f2tf32f(x1 * cs.y + x2 * cs.x);
        } else {
          w.x = f2tf32f(x1);
          w.y = f2tf32f(x2);
        }
        *(float2*)o = w;
      }
    }
  }
}

// ---------------- tensor-core causal flash attention ------------------------
// 128 q-rows per block, 8 warps (16 rows each), BN=64 keys/tile,
// K/V double-buffered cp.async. Q fragments in registers.
#define KS_STRIDE 68
#define VS_STRIDE 72
#define PS_STRIDE 68
#define KBUF (64 * KS_STRIDE)
#define VBUF (64 * VS_STRIDE)
#define FLASH_SMEM ((2 * (KBUF + VBUF) + 128 * PS_STRIDE) * 4 + 2 * 64 * 4)

__global__ __launch_bounds__(256, 2) void flash_mma_kernel(
    const float* __restrict__ Q, const float* __restrict__ K,
    const float* __restrict__ V, const int* __restrict__ amask,
    float* __restrict__ O) {
  extern __shared__ float smf[];
  float* Ksb = smf;                    // 2 buffers
  float* Vsb = Ksb + 2 * KBUF;         // 2 buffers
  float* Ps = Vsb + 2 * VBUF;          // 128 rows
  int* msk = (int*)(Ps + 128 * PS_STRIDE);  // [2][64]

  const int tid = threadIdx.x;
  const int warp = tid >> 5, lane = tid & 31;
  const int g = lane >> 2, tig = lane & 3;
  const int bx = (int)(gridDim.x - 1 - blockIdx.x);  // heavy blocks first
  const int h = blockIdx.y, b = blockIdx.z;
  const int q0 = bx << 7;
  const size_t base = (size_t)(b * NHEAD + h) * SEQ * HDIM;

  // ---- stage Q tile (128x64) through Ps, hoist fragments to registers ----
#pragma unroll
  for (int i = 0; i < 8; i++) {
    const int p = tid + (i << 8);
    const int r = p >> 4, c = (p & 15) << 2;
    *(float4*)(Ps + r * PS_STRIDE + c) =
        *(const float4*)(Q + base + (size_t)(q0 + r) * HDIM + c);
  }
  __syncthreads();
  uint32_t qf[8][4];
  {
    const float* qb = Ps + (warp * 16 + g) * PS_STRIDE;
#pragma unroll
    for (int kc = 0; kc < 8; kc++) {
      const int kk = kc << 3;
      qf[kc][0] = __float_as_uint(qb[kk + tig]);
      qf[kc][1] = __float_as_uint(qb[8 * PS_STRIDE + kk + tig]);
      qf[kc][2] = __float_as_uint(qb[kk + tig + 4]);
      qf[kc][3] = __float_as_uint(qb[8 * PS_STRIDE + kk + tig + 4]);
    }
  }
  __syncthreads();  // Ps becomes per-warp P staging

  auto prefetch = [&](int kt, int buf) {
    const int k0 = kt << 6;
    float* Ks = Ksb + buf * KBUF;
    float* Vs = Vsb + buf * VBUF;
#pragma unroll
    for (int i = 0; i < 4; i++) {
      const int p = tid + (i << 8);
      const int r = p >> 4, c = (p & 15) << 2;
      uint32_t dk = (uint32_t)__cvta_generic_to_shared(Ks + r * KS_STRIDE + c);
      CPA16(dk, K + base + (size_t)(k0 + r) * HDIM + c);
      uint32_t dv = (uint32_t)__cvta_generic_to_shared(Vs + r * VS_STRIDE + c);
      CPA16(dv, V + base + (size_t)(k0 + r) * HDIM + c);
    }
    if (tid < 64) msk[buf * 64 + tid] = amask[b * SEQ + k0 + tid];
  };

  float m0 = -1e30f, m1 = -1e30f, l0 = 0.0f, l1 = 0.0f;
  float o[8][4];
#pragma unroll
  for (int nt = 0; nt < 8; nt++)
#pragma unroll
    for (int c = 0; c < 4; c++) o[nt][c] = 0.0f;

  const int NT = (q0 >> 6) + 2;  // tiles 0..NT-1; last two are boundary tiles
  const int rg0 = q0 + warp * 16 + g;  // global row for acc slots 0/1 (+8: 2/3)

  prefetch(0, 0);
  asm volatile("cp.async.commit_group;\n");

  for (int kt = 0; kt < NT; kt++) {
    const int buf = kt & 1;
    if (kt + 1 < NT) prefetch(kt + 1, buf ^ 1);
    asm volatile("cp.async.commit_group;\n");
    asm volatile("cp.async.wait_group 1;\n");
    __syncthreads();

    const float* Ks = Ksb + buf * KBUF;
    const float* Vs = Vsb + buf * VBUF;
    const int* mk = msk + buf * 64;

    // ---- S = (Q/8) @ K^T ----
    float s[8][4];
#pragma unroll
    for (int nt = 0; nt < 8; nt++)
#pragma unroll
      for (int c = 0; c < 4; c++) s[nt][c] = 0.0f;

#pragma unroll
    for (int kc = 0; kc < 8; kc++) {
      const int kk = kc << 3;
#pragma unroll
      for (int nt = 0; nt < 8; nt++) {
        const float* kb = Ks + (nt * 8 + g) * KS_STRIDE + kk;
        uint32_t bf[2];
        bf[0] = __float_as_uint(kb[tig]);
        bf[1] = __float_as_uint(kb[tig + 4]);
        mma_tf32(s[nt], qf[kc], bf);
      }
    }

    // ---- mask ----
    if (kt >= NT - 2) {
      const int k0 = kt << 6;
#pragma unroll
      for (int nt = 0; nt < 8; nt++) {
        const int cg = k0 + nt * 8 + 2 * tig;  // global col (and +1)
        const int m_a = mk[nt * 8 + 2 * tig], m_b = mk[nt * 8 + 2 * tig + 1];
        if (!(m_a && cg <= rg0)) s[nt][0] = -1e30f;
        if (!(m_b && cg + 1 <= rg0)) s[nt][1] = -1e30f;
        if (!(m_a && cg <= rg0 + 8)) s[nt][2] = -1e30f;
        if (!(m_b && cg + 1 <= rg0 + 8)) s[nt][3] = -1e30f;
      }
    } else {
#pragma unroll
      for (int nt = 0; nt < 8; nt++) {
        const int m_a = mk[nt * 8 + 2 * tig], m_b = mk[nt * 8 + 2 * tig + 1];
        if (!m_a) { s[nt][0] = -1e30f; s[nt][2] = -1e30f; }
        if (!m_b) { s[nt][1] = -1e30f; s[nt][3] = -1e30f; }
      }
    }

    // ---- online softmax ----
    float mx0 = -1e30f, mx1 = -1e30f;
#pragma unroll
    for (int nt = 0; nt < 8; nt++) {
      mx0 = fmaxf(mx0, fmaxf(s[nt][0], s[nt][1]));
      mx1 = fmaxf(mx1, fmaxf(s[nt][2], s[nt][3]));
    }
    mx0 = fmaxf(mx0, __shfl_xor_sync(0xffffffffu, mx0, 1));
    mx0 = fmaxf(mx0, __shfl_xor_sync(0xffffffffu, mx0, 2));
    mx1 = fmaxf(mx1, __shfl_xor_sync(0xffffffffu, mx1, 1));
    mx1 = fmaxf(mx1, __shfl_xor_sync(0xffffffffu, mx1, 2));
    const float nm0 = fmaxf(m0, mx0), nm1 = fmaxf(m1, mx1);
    const float corr0 = __expf(m0 - nm0), corr1 = __expf(m1 - nm1);
    m0 = nm0;
    m1 = nm1;

    float sum0 = 0.0f, sum1 = 0.0f;
#pragma unroll
    for (int nt = 0; nt < 8; nt++) {
      s[nt][0] = __expf(s[nt][0] - nm0);
      s[nt][1] = __expf(s[nt][1] - nm0);
      s[nt][2] = __expf(s[nt][2] - nm1);
      s[nt][3] = __expf(s[nt][3] - nm1);
      sum0 += s[nt][0] + s[nt][1];
      sum1 += s[nt][2] + s[nt][3];
    }
    sum0 += __shfl_xor_sync(0xffffffffu, sum0, 1);
    sum0 += __shfl_xor_sync(0xffffffffu, sum0, 2);
    sum1 += __shfl_xor_sync(0xffffffffu, sum1, 1);
    sum1 += __shfl_xor_sync(0xffffffffu, sum1, 2);
    l0 = l0 * corr0 + sum0;
    l1 = l1 * corr1 + sum1;

#pragma unroll
    for (int nt = 0; nt < 8; nt++) {
      o[nt][0] *= corr0;
      o[nt][1] *= corr0;
      o[nt][2] *= corr1;
      o[nt][3] *= corr1;
    }

    // ---- stage P (C-layout -> A-layout) in per-warp Ps region ----
    float* pr = Ps + (warp * 16 + g) * PS_STRIDE;
#pragma unroll
    for (int nt = 0; nt < 8; nt++) {
      const int c0 = nt * 8 + 2 * tig;
      pr[c0] = f2tf32f(s[nt][0]);
      pr[c0 + 1] = f2tf32f(s[nt][1]);
      pr[8 * PS_STRIDE + c0] = f2tf32f(s[nt][2]);
      pr[8 * PS_STRIDE + c0 + 1] = f2tf32f(s[nt][3]);
    }
    __syncwarp();

    // ---- O += P @ V ----
    const float* pb = Ps + (warp * 16 + g) * PS_STRIDE;
#pragma unroll
    for (int kc = 0; kc < 8; kc++) {
      const int kk = kc << 3;
      uint32_t a[4];
      a[0] = __float_as_uint(pb[kk + tig]);
      a[1] = __float_as_uint(pb[8 * PS_STRIDE + kk + tig]);
      a[2] = __float_as_uint(pb[kk + tig + 4]);
      a[3] = __float_as_uint(pb[8 * PS_STRIDE + kk + tig + 4]);
#pragma unroll
      for (int nt = 0; nt < 8; nt++) {
        const float* vb = Vs + (kk + tig) * VS_STRIDE + nt * 8 + g;
        uint32_t bf[2];
        bf[0] = __float_as_uint(vb[0]);
        bf[1] = __float_as_uint(vb[4 * VS_STRIDE]);
        mma_tf32(o[nt], a, bf);
      }
    }
    __syncthreads();  // all warps done with Ks/Vs[buf] before refill
  }

  // ---- write O / l to [B, L, H*Dh], tf32-rounded for the proj GEMM ----
  const float inv0 = 1.0f / l0, inv1 = 1.0f / l1;
#pragma unroll
  for (int nt = 0; nt < 8; nt++) {
    const int col = h * HDIM + nt * 8 + 2 * tig;
    float2 v0 = {f2tf32f(o[nt][0] * inv0), f2tf32f(o[nt][1] * inv0)};
    float2 v1 = {f2tf32f(o[nt][2] * inv1), f2tf32f(o[nt][3] * inv1)};
    *(float2*)(O + (size_t)(b * SEQ + rg0) * EMBD + col) = v0;
    *(float2*)(O + (size_t)(b * SEQ + rg0 + 8) * EMBD + col) = v1;
  }
}

// ---------------------------------------------------------------------------
extern "C" void kernel_launch(void* const* d_in, const int* in_sizes, int n_in,
                              void* d_out, int out_size) {
  const float* x     = (const float*)d_in[0];
  const float* Wqkv  = (const float*)d_in[1];
  const float* bqkv  = (const float*)d_in[2];
  const float* Wproj = (const float*)d_in[3];
  const float* bproj = (const float*)d_in[4];
  const int*   amask = (const int*)d_in[5];
  float* out = (float*)d_out;

  float *q, *k, *v, *att, *xc, *wqkv, *wproj;
  cudaGetSymbolAddress((void**)&q, g_q);
  cudaGetSymbolAddress((void**)&k, g_k);
  cudaGetSymbolAddress((void**)&v, g_v);
  cudaGetSymbolAddress((void**)&att, g_att);
  cudaGetSymbolAddress((void**)&xc, g_xc);
  cudaGetSymbolAddress((void**)&wqkv, g_wqkv);
  cudaGetSymbolAddress((void**)&wproj, g_wproj);

  cudaFuncSetAttribute(gemm_tf32_kernel,
                       cudaFuncAttributeMaxDynamicSharedMemorySize, GEMM_SMEM);
  cudaFuncSetAttribute(gemm_qkv_rope_kernel,
                       cudaFuncAttributeMaxDynamicSharedMemorySize, GEMM_SMEM);
  cudaFuncSetAttribute(flash_mma_kernel,
                       cudaFuncAttributeMaxDynamicSharedMemorySize, FLASH_SMEM);

  // 0. RoPE cos/sin table + tf32 pre-rounding of GEMM operands
  rope_table_kernel<<<SEQ * 32 / 256, 256>>>();
  tf32_round_kernel<<<1184, 256>>>(x, xc, TOKENS * EMBD / 4);
  tf32_round_kernel<<<1184, 256>>>(Wqkv, wqkv, EMBD * QKVDIM / 4);
  tf32_round_kernel<<<1184, 256>>>(Wproj, wproj, EMBD * EMBD / 4);

  // 1. QKV projection + fused RoPE/split -> g_q (/8), g_k, g_v in [B,H,L,Dh]
  dim3 g1(QKVDIM / 128, TOKENS / 128);
  gemm_qkv_rope_kernel<<<g1, 256, GEMM_SMEM>>>(xc, wqkv, bqkv, q, k, v);

  // 2. Causal flash attention (tensor cores, BM=128) -> [B,L,D]
  dim3 g3(SEQ / 128, NHEAD, BATCH);
  flash_mma_kernel<<<g3, 256, FLASH_SMEM>>>(q, k, v, amask, att);

  // 3. Output projection: [8192,1024] @ [1024,1024]
  dim3 g4(EMBD / 128, TOKENS / 128);
  gemm_tf32_kernel<<<g4, 256, GEMM_SMEM>>>(att, wproj, bproj, out,
                                           TOKENS, EMBD, EMBD);
}